// round 17
// baseline (speedup 1.0000x reference)
#include <cuda_runtime.h>
#include <cuda_fp16.h>
#include <cstdint>
#include <cstring>

#define HH 256
#define N_NODES 8
#define N_EDGES 64
#define FEAT 1024

#define KDIM 192            // k' = rho*8+kx ; rho=ci*7+ky (0..20), pad rho>=21
#define NPX 16384           // 128x128 output plane

// repacked weights (fp16): [oc2(128)][k'(192)]
__device__ __align__(16) __half g_wcol[128 * KDIM];
// transposed fc weights: [cc(64)][f(1024)]
__device__ float g_fcT[64 * FEAT];
// BN-folded partial conv outputs (fp16): [half(2)][node(8)][oc(64)][128][128]
__device__ __half g_convh[(size_t)2 * 8 * 64 * 128 * 128];
// Pooled features per packed pair: [p(36)][ch(64)]
__device__ float g_pooled[36 * 64];
// FC features per packed pair: [p(36)][f(1024)]
__device__ float g_feat[36 * FEAT];

__device__ __forceinline__ uint32_t smem_u32(const void* p) {
    uint32_t a;
    asm("{ .reg .u64 t; cvta.to.shared.u64 t, %1; cvt.u32.u64 %0, t; }"
        : "=r"(a) : "l"(p));
    return a;
}
__device__ __forceinline__ uint32_t sw128(uint32_t o) { return o ^ ((o >> 3) & 0x70); }

__device__ __forceinline__ void ldsm_x4(uint32_t& r0, uint32_t& r1,
                                        uint32_t& r2, uint32_t& r3, uint32_t a) {
    asm volatile("ldmatrix.sync.aligned.m8n8.x4.shared.b16 {%0,%1,%2,%3}, [%4];"
                 : "=r"(r0), "=r"(r1), "=r"(r2), "=r"(r3) : "r"(a));
}
__device__ __forceinline__ void mma16816(float* c, const uint32_t* a,
                                         const uint32_t* b) {
    asm volatile("mma.sync.aligned.m16n8k16.row.col.f32.f16.f16.f32 "
                 "{%0,%1,%2,%3}, {%4,%5,%6,%7}, {%8,%9}, {%0,%1,%2,%3};"
                 : "+f"(c[0]), "+f"(c[1]), "+f"(c[2]), "+f"(c[3])
                 : "r"(a[0]), "r"(a[1]), "r"(a[2]), "r"(a[3]),
                   "r"(b[0]), "r"(b[1]));
}
#define CP_COMMIT() asm volatile("cp.async.commit_group;" ::: "memory")
#define CP_WAIT0()  asm volatile("cp.async.wait_group 0;" ::: "memory")
#define CP_WAIT1()  asm volatile("cp.async.wait_group 1;" ::: "memory")

// ---------------------------------------------------------------------------
// Kernel 0: weight repack (conv -> fp16 Wcol, padded k' layout) + fc_w transpose.
// ---------------------------------------------------------------------------
__global__ __launch_bounds__(256) void wrepack_kernel(
    const float* __restrict__ w, const float* __restrict__ fc_w)
{
    int gid = blockIdx.x * 256 + threadIdx.x;
    int stride = gridDim.x * 256;
    for (int i = gid; i < 128 * KDIM; i += stride) {
        int oc2 = i / KDIM;
        int k   = i - oc2 * KDIM;
        int hf  = oc2 >> 6;
        int oc  = oc2 & 63;
        int rho = k >> 3;
        int kx  = k & 7;
        float val = 0.f;
        if (rho < 21 && kx < 7) {
            int ci = rho / 7;
            int ky = rho - ci * 7;
            val = w[(oc * 6 + hf * 3 + ci) * 49 + ky * 7 + kx];
        }
        g_wcol[i] = __float2half_rn(val);
    }
    for (int i = gid; i < 64 * FEAT; i += stride) {
        int cc = i >> 10;
        int f  = i & (FEAT - 1);
        g_fcT[i] = fc_w[f * 64 + cc];
    }
}

// ---------------------------------------------------------------------------
// Kernel 1: fused im2col + HMMA GEMM.  CTA = (py, M-half, node); 8 warps =
// 2m x 4n, warp tile 32x32 (acc 32 regs -> 3 CTAs/SM).  A fragments read
// directly from a 21x140 slab window; B double-buffered via cp.async.
// ---------------------------------------------------------------------------
#define SLAB_C    140           // slab cols (133 used), even stride
#define DOFF_SC   0
#define DOFF_SH   512
#define DOFF_SLAB 1024          // 24*140*2 = 6720 -> ends 7744
#define DOFF_B0   7808
#define DOFF_B1   24192
#define DSMEM_TOT 40576
#define EPI_STRIDE 72           // epi overlay at 1024: 128*72*2=18432 B

__device__ __forceinline__ void stage_B(uint32_t sb_u, int ck, int tid)
{
    #pragma unroll
    for (int ii = 0; ii < 4; ii++) {
        int i = ii * 256 + tid;
        int g = i & 7, r = i >> 3;
        const void* bsrc = g_wcol + (size_t)r * KDIM + ck * 64 + g * 8;
        asm volatile("cp.async.cg.shared.global [%0], [%1], 16;"
                     :: "r"(sb_u + sw128(r * 128 + g * 16)), "l"(bsrc));
    }
}

__device__ __forceinline__ void mma_chunk(
    const __half* s_slab, uint32_t sb, int ck, int ksteps,
    float (&acc)[2][4][4], int warp_m, int b_row, int b_kbh, int lid)
{
    const int gid = lid >> 2;
    const int tig = lid & 3;
    #pragma unroll
    for (int s = 0; s < 4; s++) {
        if (s >= ksteps) break;
        uint32_t bf[4][2];
        #pragma unroll
        for (int np = 0; np < 2; np++) {
            uint32_t addr = sb + sw128((b_row + np * 16) * 128
                                       + (s * 2 + b_kbh) * 16);
            uint32_t r0, r1, r2, r3;
            ldsm_x4(r0, r1, r2, r3, addr);
            bf[np * 2][0] = r0;     bf[np * 2][1] = r1;
            bf[np * 2 + 1][0] = r2; bf[np * 2 + 1][1] = r3;
        }
        const int rho0 = ck * 8 + 2 * s;
        const __half* arow = s_slab + rho0 * SLAB_C
                             + 2 * (warp_m * 32 + gid) + 2 * tig;
        #pragma unroll
        for (int mt = 0; mt < 2; mt++) {
            const __half* pa = arow + 32 * mt;
            uint32_t af[4];
            af[0] = *(const uint32_t*)pa;
            af[1] = *(const uint32_t*)(pa + 16);
            af[2] = *(const uint32_t*)(pa + SLAB_C);
            af[3] = *(const uint32_t*)(pa + SLAB_C + 16);
            #pragma unroll
            for (int nt = 0; nt < 4; nt++)
                mma16816(acc[mt][nt], af, bf[nt]);
        }
    }
}

__global__ __launch_bounds__(256, 3) void gemm_kernel(
    const float* __restrict__ x,
    const float* __restrict__ bn_g, const float* __restrict__ bn_b,
    const float* __restrict__ bn_m, const float* __restrict__ bn_v)
{
    extern __shared__ __align__(128) char dsm[];
    float* s_sc = (float*)(dsm + DOFF_SC);
    float* s_sh = (float*)(dsm + DOFF_SH);
    __half* s_slab = (__half*)(dsm + DOFF_SLAB);
    const uint32_t sbu0 = smem_u32(dsm + DOFF_B0);
    const uint32_t sbu1 = smem_u32(dsm + DOFF_B1);

    const int tid  = threadIdx.x;
    const int wid  = tid >> 5;
    const int lid  = tid & 31;
    const int py   = blockIdx.x;
    const int mh   = blockIdx.y;          // M half: px 64*mh .. +63
    const int node = blockIdx.z;

    stage_B(sbu0, 0, tid);
    CP_COMMIT();
    stage_B(sbu1, 1, tid);
    CP_COMMIT();

    if (tid < 128) {
        int hf = tid >> 6, oc = tid & 63;
        float rs = rsqrtf(bn_v[oc] + 1e-5f);
        float sc = bn_g[oc] * rs;
        s_sc[tid] = sc;
        s_sh[tid] = hf ? (bn_b[oc] - bn_m[oc] * sc) : 0.f;
    }
    // slab window: rho 0..20, cols 128*mh-3 .. +136 (133 used)
    for (int i = tid; i < 21 * SLAB_C; i += 256) {
        int rho = i / SLAB_C;
        int cc  = i - rho * SLAB_C;
        int ci  = rho / 7;
        int ry  = rho - ci * 7;
        int r = 2 * py - 3 + ry;
        int c = 128 * mh - 3 + cc;
        float v = 0.f;
        if (r >= 0 && r < HH && c >= 0 && c < HH)
            v = x[((size_t)(node * 3 + ci) * HH + r) * HH + c];
        s_slab[i] = __float2half_rn(v);
    }
    for (int i = tid; i < 3 * SLAB_C; i += 256)
        s_slab[21 * SLAB_C + i] = __ushort_as_half((unsigned short)0);

    const int warp_m = wid >> 2;          // 0..1 (32 rows each)
    const int warp_n = wid & 3;           // 0..3 (32 cols each)

    float acc[2][4][4];
    #pragma unroll
    for (int mt = 0; mt < 2; mt++)
        #pragma unroll
        for (int nt = 0; nt < 4; nt++)
            #pragma unroll
            for (int q = 0; q < 4; q++) acc[mt][nt][q] = 0.f;

    const int b_row = warp_n * 32 + (lid & 7) + ((lid >> 4) << 3);
    const int b_kbh = (lid >> 3) & 1;

    CP_WAIT1();                           // B0 arrived
    __syncthreads();                      // slab + B0 visible

    mma_chunk(s_slab, sbu0, 0, 4, acc, warp_m, b_row, b_kbh, lid);
    CP_WAIT0();                           // B1 arrived
    __syncthreads();                      // all warps done with B0
    stage_B(sbu0, 2, tid);                // reuse B0 for chunk 2
    CP_COMMIT();
    mma_chunk(s_slab, sbu1, 1, 4, acc, warp_m, b_row, b_kbh, lid);
    CP_WAIT0();
    __syncthreads();
    mma_chunk(s_slab, sbu0, 2, 3, acc, warp_m, b_row, b_kbh, lid);

    // ---- epilogue: BN fold -> padded smem -> coalesced copy-out ----
    __syncthreads();
    __half* epi = (__half*)(dsm + DOFF_SLAB);
    const int g   = lid >> 2;
    const int tig = lid & 3;

    #pragma unroll
    for (int nt = 0; nt < 4; nt++) {
        #pragma unroll
        for (int half_c = 0; half_c < 2; half_c++) {
            int oc2 = warp_n * 32 + nt * 8 + tig * 2 + half_c;
            float sc = s_sc[oc2], sh = s_sh[oc2];
            #pragma unroll
            for (int mt = 0; mt < 2; mt++) {
                int pxl = warp_m * 32 + g + mt * 16;
                epi[oc2 * EPI_STRIDE + pxl] =
                    __float2half_rn(acc[mt][nt][half_c] * sc + sh);
                epi[oc2 * EPI_STRIDE + pxl + 8] =
                    __float2half_rn(acc[mt][nt][half_c + 2] * sc + sh);
            }
        }
    }
    __syncthreads();

    {
        int oc2 = tid >> 1, seg = tid & 1;
        int hf = oc2 >> 6, oc = oc2 & 63;
        __half* dst = g_convh + ((size_t)(hf * 8 + node) * 64 + oc) * NPX
                      + py * 128 + mh * 64 + seg * 32;
        const uint4* src = (const uint4*)(epi + oc2 * EPI_STRIDE + seg * 32);
        #pragma unroll
        for (int q = 0; q < 4; q++)
            ((uint4*)dst)[q] = src[q];
    }
}

// ---------------------------------------------------------------------------
// Kernel 2: per-(pair, channel) pool (R11 known-good).
// ---------------------------------------------------------------------------
__global__ __launch_bounds__(256) void pool_kernel()
{
    __shared__ __half s_hm[65][68];
    __shared__ float s_red[8];

    const int c   = blockIdx.x;
    const int tid = threadIdx.x;

    int p = blockIdx.y;
    int i = 0, base = 0;
    while (p >= base + (8 - i)) { base += 8 - i; i++; }
    int j = i + (p - base);

    const __half* pA = g_convh + ((size_t)(0 * 8 + i) * 64 + c) * NPX;
    const __half* pB = g_convh + ((size_t)(1 * 8 + j) * 64 + c) * NPX;

    const __half2 z2 = __floats2half2_rn(0.f, 0.f);
    float sum = 0.f;

    #pragma unroll
    for (int phase = 0; phase < 2; phase++) {
        __syncthreads();
        const int gbase  = phase ? 63 : 0;
        const int sbase  = phase ? 0 : 1;
        const int nrows  = phase ? 65 : 64;
        if (phase == 0 && tid < 64) s_hm[0][tid] = __ushort_as_half(0);

        const int total = nrows * 16;
        const int iters = (total + 255) >> 8;
        for (int it = 0; it < iters; it++) {
            int t = it * 256 + tid;
            bool act = t < total;
            int r   = t >> 4;
            int c16 = t & 15;
            uint4 av = make_uint4(0, 0, 0, 0), bv = av;
            if (act) {
                av = *(const uint4*)(pA + (gbase + r) * 128 + c16 * 8);
                bv = *(const uint4*)(pB + (gbase + r) * 128 + c16 * 8);
            }
            const __half2* ah = (const __half2*)&av;
            const __half2* bh = (const __half2*)&bv;
            __half2 xx[4];
            #pragma unroll
            for (int q = 0; q < 4; q++)
                xx[q] = __hmax2(__hadd2(ah[q], bh[q]), z2);

            unsigned hi3 = __half_as_ushort(__high2half(xx[3]));
            unsigned left = __shfl_up_sync(0xffffffffu, hi3, 1);
            __half xl = (c16 == 0) ? __ushort_as_half(0)
                                   : __ushort_as_half((unsigned short)left);
            __half hm0 = __hmax(__hmax(__low2half(xx[0]), __high2half(xx[0])), xl);
            __half hm1 = __hmax(__hmax(__low2half(xx[1]), __high2half(xx[1])),
                                __high2half(xx[0]));
            __half hm2 = __hmax(__hmax(__low2half(xx[2]), __high2half(xx[2])),
                                __high2half(xx[1]));
            __half hm3 = __hmax(__hmax(__low2half(xx[3]), __high2half(xx[3])),
                                __high2half(xx[2]));
            if (act) {
                __align__(8) __half hv[4] = {hm0, hm1, hm2, hm3};
                uint2 bits;
                memcpy(&bits, hv, 8);
                *(uint2*)(&s_hm[sbase + r][c16 * 4]) = bits;
            }
        }
        __syncthreads();

        for (int t = tid; t < 1024; t += 256) {
            int pyl = t >> 5;
            int pop = t & 31;
            const __half2* r0 = (const __half2*)&s_hm[2 * pyl][0];
            const __half2* r1 = (const __half2*)&s_hm[2 * pyl + 1][0];
            const __half2* r2 = (const __half2*)&s_hm[2 * pyl + 2][0];
            __half2 m2 = __hmax2(r0[pop], __hmax2(r1[pop], r2[pop]));
            float2 f = __half22float2(m2);
            sum += f.x + f.y;
        }
    }

    #pragma unroll
    for (int o = 16; o > 0; o >>= 1)
        sum += __shfl_down_sync(0xffffffffu, sum, o);
    if ((tid & 31) == 0) s_red[tid >> 5] = sum;
    __syncthreads();
    if (tid == 0) {
        float t = 0.f;
        #pragma unroll
        for (int q = 0; q < 8; q++) t += s_red[q];
        g_pooled[p * 64 + c] = t * (1.f / 4096.f);
    }
}

// ---------------------------------------------------------------------------
// Kernel 3a: fc(64->1024)+ReLU per packed pair.  grid (4, 36), 256 thr.
// 4 independent partial sums break the 64-FMA dependency chain.
// ---------------------------------------------------------------------------
__global__ __launch_bounds__(256) void fc_kernel(const float* __restrict__ fc_b)
{
    __shared__ float s_p[64];
    const int p = blockIdx.y;
    const int f = blockIdx.x * 256 + threadIdx.x;
    if (threadIdx.x < 64) s_p[threadIdx.x] = g_pooled[p * 64 + threadIdx.x];
    __syncthreads();

    float a0 = 0.f, a1 = 0.f, a2 = 0.f, a3 = 0.f;
    #pragma unroll
    for (int cc = 0; cc < 64; cc += 4) {
        a0 += s_p[cc]     * g_fcT[cc * FEAT + f];
        a1 += s_p[cc + 1] * g_fcT[(cc + 1) * FEAT + f];
        a2 += s_p[cc + 2] * g_fcT[(cc + 2) * FEAT + f];
        a3 += s_p[cc + 3] * g_fcT[(cc + 3) * FEAT + f];
    }
    float a = fc_b[f] + ((a0 + a1) + (a2 + a3));
    g_feat[p * FEAT + f] = fmaxf(a, 0.f);
}

// ---------------------------------------------------------------------------
// Kernel 3b: heads (1024->6) + edge scatter.  grid 36, 256 thr.
// ---------------------------------------------------------------------------
__global__ __launch_bounds__(256) void heads_scatter_kernel(
    const int*   __restrict__ edge_index,
    const float* __restrict__ xyz_w,  const float* __restrict__ xyz_b,
    const float* __restrict__ wpqr_w, const float* __restrict__ wpqr_b,
    float* __restrict__ out, int out_size)
{
    __shared__ float s_f[FEAT];
    __shared__ float s_red[6][8];
    __shared__ float s_out[6];

    const int pp  = blockIdx.x;
    const int tid = threadIdx.x;

    #pragma unroll
    for (int q = 0; q < 4; q++)
        s_f[tid + q * 256] = g_feat[pp * FEAT + tid + q * 256];
    __syncthreads();

    float acc[6] = {0, 0, 0, 0, 0, 0};
    #pragma unroll
    for (int q = 0; q < 4; q++) {
        int f = tid + q * 256;
        float v = s_f[f];
        acc[0] += v * xyz_w[f];
        acc[1] += v * xyz_w[FEAT + f];
        acc[2] += v * xyz_w[2 * FEAT + f];
        acc[3] += v * wpqr_w[f];
        acc[4] += v * wpqr_w[FEAT + f];
        acc[5] += v * wpqr_w[2 * FEAT + f];
    }
    #pragma unroll
    for (int o = 0; o < 6; o++) {
        float v = acc[o];
        #pragma unroll
        for (int sft = 16; sft > 0; sft >>= 1)
            v += __shfl_down_sync(0xffffffffu, v, sft);
        if ((tid & 31) == 0) s_red[o][tid >> 5] = v;
    }
    __syncthreads();
    if (tid < 6) {
        float t = 0.f;
        #pragma unroll
        for (int q = 0; q < 8; q++) t += s_red[tid][q];
        t += (tid < 3) ? xyz_b[tid] : wpqr_b[tid - 3];
        s_out[tid] = t;
    }
    __syncthreads();

    int offs = out_size - N_EDGES * 6;
    for (int idx = tid; idx < out_size; idx += 256) {
        int rel = (idx < offs) ? idx : idx - offs;
        int e = rel / 6, o = rel - e * 6;
        int a0 = edge_index[e], a1 = edge_index[N_EDGES + e];
        int i = min(a0, a1), j = max(a0, a1);
        int pk = 8 * i - (i * (i - 1)) / 2 + (j - i);
        if (pk == pp) out[idx] = s_out[o];
    }
}

// ---------------------------------------------------------------------------
extern "C" void kernel_launch(void* const* d_in, const int* in_sizes, int n_in,
                              void* d_out, int out_size)
{
    const float* x       = (const float*)d_in[0];
    const int*   ei      = (const int*)  d_in[1];
    const float* conv1_w = (const float*)d_in[2];
    const float* bn_g    = (const float*)d_in[3];
    const float* bn_b    = (const float*)d_in[4];
    const float* bn_m    = (const float*)d_in[5];
    const float* bn_v    = (const float*)d_in[6];
    const float* fc_w    = (const float*)d_in[7];
    const float* fc_b    = (const float*)d_in[8];
    const float* xyz_w   = (const float*)d_in[9];
    const float* xyz_b   = (const float*)d_in[10];
    const float* wpqr_w  = (const float*)d_in[11];
    const float* wpqr_b  = (const float*)d_in[12];
    float* out = (float*)d_out;

    cudaFuncSetAttribute(gemm_kernel,
                         cudaFuncAttributeMaxDynamicSharedMemorySize, DSMEM_TOT);

    wrepack_kernel<<<336, 256>>>(conv1_w, fc_w);
    gemm_kernel<<<dim3(128, 2, 8), 256, DSMEM_TOT>>>(x, bn_g, bn_b, bn_m, bn_v);
    pool_kernel<<<dim3(64, 36), 256>>>();
    fc_kernel<<<dim3(4, 36), 256>>>(fc_b);
    heads_scatter_kernel<<<36, 256>>>(ei, xyz_w, xyz_b, wpqr_w, wpqr_b,
                                      out, out_size);
}